// round 8
// baseline (speedup 1.0000x reference)
#include <cuda_runtime.h>
#include <cuda_fp16.h>
#include <cstdint>

#define SEQ 384
#define CIN 512
#define HW  64
#define NH  8
#define HD  64
#define K9  (CIN * 9)        // 4608
#define BP  512              // NH * HW batch-pairs
#define NROWS (SEQ * HW)     // 24576 GEMM rows
#define SS2 (SEQ * SEQ)      // 147456

// Scratch (device globals; no runtime allocation)
__device__ uint32_t g_feats_hl[(size_t)4 * BP * SEQ * HD];  // [e][bp][n][dd] packed(hi,lo)
__device__ uint32_t g_vT[(size_t)BP * HD * SEQ];            // [bp][dd][n]   packed(hi,lo)
__device__ float    g_S[2ull * BP * SS2];                   // [v][bp][q][k] scores
__device__ uint32_t g_attn[(size_t)BP * SS2];               // blended attn, packed(hi,lo)
__device__ uint32_t g_c2_hl[(size_t)SEQ * CIN * HW];        // conv2 input, packed(hi,lo)
__device__ __half   g_Ah[(size_t)NROWS * K9];               // im2col hi plane (k' = r*512+ci)
__device__ __half   g_Al[(size_t)NROWS * K9];               // im2col lo plane
__device__ __half   g_wh_in[(size_t)2560 * K9];             // weights hi, k'-order
__device__ __half   g_wl_in[(size_t)2560 * K9];
__device__ __half   g_wh_out[(size_t)512 * K9];
__device__ __half   g_wl_out[(size_t)512 * K9];

// ---------------------------------------------------------------------------
// helpers
// ---------------------------------------------------------------------------
__device__ __forceinline__ uint32_t split_h2(float x)
{
    __half hi = __float2half_rn(x);
    __half lo = __float2half_rn(x - __half2float(hi));
    return (uint32_t)__half_as_ushort(hi) | ((uint32_t)__half_as_ushort(lo) << 16);
}

__device__ __forceinline__ void mma_f16(float c[4], const uint32_t a[4],
                                        uint32_t b0, uint32_t b1)
{
    asm volatile(
        "mma.sync.aligned.m16n8k16.row.col.f32.f16.f16.f32 "
        "{%0,%1,%2,%3}, {%4,%5,%6,%7}, {%8,%9}, {%0,%1,%2,%3};"
        : "+f"(c[0]), "+f"(c[1]), "+f"(c[2]), "+f"(c[3])
        : "r"(a[0]), "r"(a[1]), "r"(a[2]), "r"(a[3]), "r"(b0), "r"(b1));
}
__device__ __forceinline__ void ldsm4(uint32_t& r0, uint32_t& r1, uint32_t& r2,
                                      uint32_t& r3, uint32_t addr)
{
    asm volatile("ldmatrix.sync.aligned.m8n8.x4.shared.b16 {%0,%1,%2,%3}, [%4];"
                 : "=r"(r0), "=r"(r1), "=r"(r2), "=r"(r3) : "r"(addr));
}
__device__ __forceinline__ void cpa16(uint32_t dst, const void* src)
{
    asm volatile("cp.async.cg.shared.global [%0], [%1], 16;" :: "r"(dst), "l"(src));
}

// ---------------------------------------------------------------------------
// Weight split + permute to k' = r*512 + ci order
// ---------------------------------------------------------------------------
__global__ void split_w_kernel(const float* __restrict__ w,
                               __half* __restrict__ wh, __half* __restrict__ wl, int n)
{
    int i = blockIdx.x * 256 + threadIdx.x;
    if (i >= n) return;
    int co = i / K9;
    int kn = i - co * K9;
    int r = kn >> 9, ci = kn & 511;
    float x = w[(size_t)co * K9 + ci * 9 + r];
    __half hi = __float2half_rn(x);
    wh[i] = hi;
    wl[i] = __float2half_rn(x - __half2float(hi));
}

// ---------------------------------------------------------------------------
// im2col expansion into hi/lo fp16 planes, k' = r*512 + ci.
// ---------------------------------------------------------------------------
template <bool PACKED>
__global__ __launch_bounds__(256) void im2col_kernel(const float* __restrict__ srcF)
{
    __shared__ ushort th[64][72];
    __shared__ ushort tl[64][72];
    const int n   = blockIdx.x;
    const int ci0 = blockIdx.y * 64;
    const int t   = threadIdx.x;

    {
        int sp4 = (t & 15) * 4;
        int ciL = t >> 4;
        #pragma unroll
        for (int pass = 0; pass < 4; pass++) {
            int ci = pass * 16 + ciL;
            if (PACKED) {
                uint4 w = *(const uint4*)(g_c2_hl + ((size_t)n * CIN + ci0 + ci) * 64 + sp4);
                uint32_t ws[4] = {w.x, w.y, w.z, w.w};
                #pragma unroll
                for (int j = 0; j < 4; j++) {
                    th[sp4 + j][ci] = (ushort)(ws[j] & 0xFFFF);
                    tl[sp4 + j][ci] = (ushort)(ws[j] >> 16);
                }
            } else {
                float4 v = *(const float4*)(srcF + ((size_t)n * CIN + ci0 + ci) * 64 + sp4);
                float vs[4] = {v.x, v.y, v.z, v.w};
                #pragma unroll
                for (int j = 0; j < 4; j++) {
                    __half hi = __float2half_rn(vs[j]);
                    __half lo = __float2half_rn(vs[j] - __half2float(hi));
                    th[sp4 + j][ci] = __half_as_ushort(hi);
                    tl[sp4 + j][ci] = __half_as_ushort(lo);
                }
            }
        }
    }
    __syncthreads();

    const int ciQ = t & 15;
    const int rg  = t >> 4;
    #pragma unroll
    for (int si = 0; si < 4; si++) {
        int sp = si * 16 + rg;
        int yy = sp >> 3, xx = sp & 7;
        size_t obase = (size_t)(n * 64 + sp) * K9 + ci0 + ciQ * 4;
        #pragma unroll
        for (int r = 0; r < 9; r++) {
            int y = yy + r / 3 - 1, x = xx + r % 3 - 1;
            uint2 vh = make_uint2(0, 0), vl = make_uint2(0, 0);
            if ((unsigned)y < 8u && (unsigned)x < 8u) {
                int spp = y * 8 + x;
                vh = *(const uint2*)&th[spp][ciQ * 4];
                vl = *(const uint2*)&tl[spp][ciQ * 4];
            }
            *(uint2*)&g_Ah[obase + (size_t)r * 512] = vh;
            *(uint2*)&g_Al[obase + (size_t)r * 512] = vl;
        }
    }
}

// ---------------------------------------------------------------------------
// fp16x3 GEMM conv: single barrier per stage + B-fragment software pipeline.
// ---------------------------------------------------------------------------
#define LDK2 20
#define STG_BYTES (4 * 128 * LDK2 * 4)
#define SMEM_BYTES (2 * STG_BYTES)

__device__ __forceinline__ void conv_fill(uint32_t base, int row0, int co0, int k0,
                                          int tid, const __half* gwh, const __half* gwl)
{
    #pragma unroll
    for (int h = 0; h < 2; h++) {
        int c = h * 256 + tid;
        int row = c >> 2, q = c & 3;
        uint32_t doff = (uint32_t)((row * LDK2 + q * 4) * 4);
        size_t aoff = (size_t)(row0 + row) * K9 + k0 + q * 8;
        size_t boff = (size_t)(co0 + row) * K9 + k0 + q * 8;
        cpa16(base + doff,         g_Ah + aoff);
        cpa16(base + 10240 + doff, g_Al + aoff);
        cpa16(base + 20480 + doff, gwh + boff);
        cpa16(base + 30720 + doff, gwl + boff);
    }
    asm volatile("cp.async.commit_group;" ::: "memory");
}

template <int CO, bool FIRST>
__global__ void __launch_bounds__(256, 2)
conv_f16_kernel(const __half* __restrict__ gwh,
                const __half* __restrict__ gwl,
                const float* __restrict__ bias,
                float* __restrict__ out)
{
    extern __shared__ uint32_t sm[];
    const uint32_t smb = (uint32_t)__cvta_generic_to_shared(sm);

    const int row0 = blockIdx.y * 128;
    const int co0  = blockIdx.x * 128;
    const int tid  = threadIdx.x;
    const int lane = tid & 31, wid = tid >> 5;
    const int rbase = (wid >> 1) * 32;
    const int cbase = (wid & 1) * 64;
    const int lg = lane >> 2, lt = lane & 3;

    const int aRow = lane & 15, aCol = (lane >> 4) * 4;
    const int bRow = ((lane >> 4) & 1) * 8 + (lane & 7);
    const int bCol = ((lane >> 3) & 1) * 4;

    float acc[2][8][4] = {};

    conv_fill(smb, row0, co0, 0, tid, gwh, gwl);

    const int NITER = K9 / 32;
    for (int it = 0; it < NITER; it++) {
        const int s = it & 1;
        asm volatile("cp.async.wait_group 0;" ::: "memory");
        __syncthreads();
        // Safe: every warp has finished compute(it-1) (it precedes this barrier),
        // so refilling the other buffer needs no trailing barrier.
        if (it + 1 < NITER)
            conv_fill(smb + (1 - s) * STG_BYTES, row0, co0, (it + 1) * 32, tid, gwh, gwl);

        const uint32_t base = smb + s * STG_BYTES;
        #pragma unroll
        for (int k16 = 0; k16 < 2; k16++) {
            const uint32_t ko = k16 * 8;
            uint32_t ah[2][4], al[2][4];
            #pragma unroll
            for (int mt = 0; mt < 2; mt++) {
                uint32_t aw = base + ((rbase + mt * 16 + aRow) * LDK2 + aCol + ko) * 4;
                ldsm4(ah[mt][0], ah[mt][1], ah[mt][2], ah[mt][3], aw);
                ldsm4(al[mt][0], al[mt][1], al[mt][2], al[mt][3], aw + 10240);
            }
            // B fragments: double-buffered, loaded one pr ahead of use
            uint32_t bf[2][8];
            {
                uint32_t bw = base + 20480 + ((cbase + bRow) * LDK2 + bCol + ko) * 4;
                ldsm4(bf[0][0], bf[0][1], bf[0][2], bf[0][3], bw);
                ldsm4(bf[0][4], bf[0][5], bf[0][6], bf[0][7], bw + 10240);
            }
            #pragma unroll
            for (int pr = 0; pr < 4; pr++) {
                if (pr < 3) {
                    uint32_t bw = base + 20480 +
                                  ((cbase + (pr + 1) * 16 + bRow) * LDK2 + bCol + ko) * 4;
                    uint32_t* d = bf[(pr + 1) & 1];
                    ldsm4(d[0], d[1], d[2], d[3], bw);
                    ldsm4(d[4], d[5], d[6], d[7], bw + 10240);
                }
                const uint32_t* b = bf[pr & 1];
                #pragma unroll
                for (int mt = 0; mt < 2; mt++) {
                    mma_f16(acc[mt][2 * pr],     ah[mt], b[0], b[1]);
                    mma_f16(acc[mt][2 * pr],     ah[mt], b[4], b[5]);
                    mma_f16(acc[mt][2 * pr],     al[mt], b[0], b[1]);
                    mma_f16(acc[mt][2 * pr + 1], ah[mt], b[2], b[3]);
                    mma_f16(acc[mt][2 * pr + 1], ah[mt], b[6], b[7]);
                    mma_f16(acc[mt][2 * pr + 1], al[mt], b[2], b[3]);
                }
            }
        }
        // no trailing __syncthreads()
    }

    // ---- epilogue ----
    #pragma unroll
    for (int mt = 0; mt < 2; mt++) {
        #pragma unroll
        for (int nt = 0; nt < 8; nt++) {
            #pragma unroll
            for (int cp = 0; cp < 4; cp++) {
                int row = row0 + rbase + mt * 16 + lg + ((cp >= 2) ? 8 : 0);
                int col = cbase + nt * 8 + lt * 2 + (cp & 1);
                int co  = co0 + col;
                float v = acc[mt][nt][cp] + bias[co];
                int n = row >> 6, sp = row & 63;
                if (FIRST) {
                    int e  = co >> 9;
                    int dd = (co >> 3) & 63;
                    int hh = co & 7;
                    int bpi = hh * 64 + sp;
                    uint32_t pv = split_h2(v);
                    if (e < 4)
                        g_feats_hl[(((size_t)e * BP + bpi) * SEQ + n) * HD + dd] = pv;
                    else
                        g_vT[((size_t)bpi * HD + dd) * SEQ + n] = pv;
                } else {
                    out[((size_t)n * CO + co) * 64 + sp] = v;
                }
            }
        }
    }
}

// ---------------------------------------------------------------------------
// QK on fp16x3 MMA: S[v][bp][q][k] = 0.125*dot(Q_{2+v},K_v) + mask.
// ---------------------------------------------------------------------------
#define QK_SMEM (4 * 4608 * 4)   // 73728 bytes

__global__ void __launch_bounds__(256, 2)
qk_mma_kernel(const float* __restrict__ am)
{
    extern __shared__ uint32_t sm[];
    const uint32_t smb = (uint32_t)__cvta_generic_to_shared(sm);

    const int bpv = blockIdx.z, bp = bpv >> 1, v = bpv & 1, head = bp >> 6;
    const int m0 = blockIdx.y * 128, n0 = blockIdx.x * 128;
    const int tid = threadIdx.x, lane = tid & 31, wid = tid >> 5;
    const int rbase = (wid >> 1) * 32, cbase = (wid & 1) * 64;
    const int lg = lane >> 2, lt = lane & 3;
    const int aRow = lane & 15, aCol = (lane >> 4) * 4;
    const int bRow = ((lane >> 4) & 1) * 8 + (lane & 7);
    const int bCol = ((lane >> 3) & 1) * 4;

    const uint32_t* Q  = g_feats_hl + (((size_t)(2 + v) * BP + bp) * SEQ + m0) * HD;
    const uint32_t* Kp = g_feats_hl + (((size_t)v * BP + bp) * SEQ + n0) * HD;

    #pragma unroll
    for (int i = 0; i < 8; i++) {
        int lin = i * 256 + tid;
        int row = lin >> 4, q4 = lin & 15;
        uint4 wq = *(const uint4*)(Q  + (size_t)row * HD + q4 * 4);
        uint4 wk = *(const uint4*)(Kp + (size_t)row * HD + q4 * 4);
        int o = row * 36 + q4 * 2;
        *(uint2*)&sm[o]         = make_uint2(__byte_perm(wq.x, wq.y, 0x5410),
                                             __byte_perm(wq.z, wq.w, 0x5410));
        *(uint2*)&sm[4608 + o]  = make_uint2(__byte_perm(wq.x, wq.y, 0x7632),
                                             __byte_perm(wq.z, wq.w, 0x7632));
        *(uint2*)&sm[9216 + o]  = make_uint2(__byte_perm(wk.x, wk.y, 0x5410),
                                             __byte_perm(wk.z, wk.w, 0x5410));
        *(uint2*)&sm[13824 + o] = make_uint2(__byte_perm(wk.x, wk.y, 0x7632),
                                             __byte_perm(wk.z, wk.w, 0x7632));
    }
    __syncthreads();

    float acc[2][8][4] = {};
    #pragma unroll
    for (int k16 = 0; k16 < 4; k16++) {
        const int ko = k16 * 8;
        uint32_t ah[2][4], al[2][4];
        #pragma unroll
        for (int mt = 0; mt < 2; mt++) {
            uint32_t aw = smb + ((rbase + mt * 16 + aRow) * 36 + aCol + ko) * 4;
            ldsm4(ah[mt][0], ah[mt][1], ah[mt][2], ah[mt][3], aw);
            ldsm4(al[mt][0], al[mt][1], al[mt][2], al[mt][3], aw + 18432);
        }
        #pragma unroll
        for (int pr = 0; pr < 4; pr++) {
            uint32_t bw = smb + 36864 + ((cbase + pr * 16 + bRow) * 36 + bCol + ko) * 4;
            uint32_t bh0, bh1, bh2, bh3, bl0, bl1, bl2, bl3;
            ldsm4(bh0, bh1, bh2, bh3, bw);
            ldsm4(bl0, bl1, bl2, bl3, bw + 18432);
            #pragma unroll
            for (int mt = 0; mt < 2; mt++) {
                mma_f16(acc[mt][2 * pr],     ah[mt], bh0, bh1);
                mma_f16(acc[mt][2 * pr],     ah[mt], bl0, bl1);
                mma_f16(acc[mt][2 * pr],     al[mt], bh0, bh1);
                mma_f16(acc[mt][2 * pr + 1], ah[mt], bh2, bh3);
                mma_f16(acc[mt][2 * pr + 1], ah[mt], bl2, bl3);
                mma_f16(acc[mt][2 * pr + 1], al[mt], bh2, bh3);
            }
        }
    }

    float* Sout = g_S + ((size_t)v * BP + bp) * SS2;
    const float* amr = am + (size_t)head * SS2;
    #pragma unroll
    for (int mt = 0; mt < 2; mt++) {
        #pragma unroll
        for (int nt = 0; nt < 8; nt++) {
            #pragma unroll
            for (int cp = 0; cp < 4; cp++) {
                int q  = m0 + rbase + mt * 16 + lg + ((cp >= 2) ? 8 : 0);
                int kk = n0 + cbase + nt * 8 + lt * 2 + (cp & 1);
                Sout[(size_t)q * SEQ + kk] =
                    acc[mt][nt][cp] * 0.125f + amr[(size_t)q * SEQ + kk];
            }
        }
    }
}

// ---------------------------------------------------------------------------
// Dual softmax + agent-aware blend; writes packed split attn to g_attn.
// ---------------------------------------------------------------------------
__global__ __launch_bounds__(128) void softmax_kernel(const int* __restrict__ agent)
{
    __shared__ float red[128];
    const int q = blockIdx.x, bp = blockIdx.y, head = bp >> 6;
    const int t = threadIdx.x;

    const size_t base = ((size_t)bp * SEQ + q) * SEQ;
    const float* Ss = g_S + base;
    const float* So = g_S + (size_t)BP * SS2 + base;
    uint32_t* Aout = g_attn + base;
    const int* mrow = agent + ((size_t)head * SEQ + q) * SEQ;

    float s0 = Ss[t], s1 = Ss[t + 128], s2 = Ss[t + 256];
    float o0 = So[t], o1 = So[t + 128], o2 = So[t + 256];

    auto bred = [&](float val, bool ismax) -> float {
        red[t] = val; __syncthreads();
        #pragma unroll
        for (int w = 64; w > 0; w >>= 1) {
            if (t < w) red[t] = ismax ? fmaxf(red[t], red[t + w]) : (red[t] + red[t + w]);
            __syncthreads();
        }
        float r = red[0]; __syncthreads();
        return r;
    };

    float Ms = bred(fmaxf(s0, fmaxf(s1, s2)), true);
    float Mo = bred(fmaxf(o0, fmaxf(o1, o2)), true);

    s0 = __expf(s0 - Ms); s1 = __expf(s1 - Ms); s2 = __expf(s2 - Ms);
    o0 = __expf(o0 - Mo); o1 = __expf(o1 - Mo); o2 = __expf(o2 - Mo);

    float Zs = bred(s0 + s1 + s2, false);
    float Zo = bred(o0 + o1 + o2, false);
    float rs = 1.f / Zs, ro = 1.f / Zo;

    float m0 = (float)mrow[t], m1 = (float)mrow[t + 128], m2 = (float)mrow[t + 256];
    Aout[t]       = split_h2(m0 * s0 * rs + (1.f - m0) * o0 * ro);
    Aout[t + 128] = split_h2(m1 * s1 * rs + (1.f - m1) * o1 * ro);
    Aout[t + 256] = split_h2(m2 * s2 * rs + (1.f - m2) * o2 * ro);
}

// ---------------------------------------------------------------------------
// AV on fp16x3 MMA: O[bp][q][dd] = sum_k attn[q][k] * V[k][dd].
// ---------------------------------------------------------------------------
#define AV_SMEM (13824 * 4)   // 55296 bytes

__global__ void __launch_bounds__(256, 2)
av_mma_kernel()
{
    extern __shared__ uint32_t sm[];
    const uint32_t smb = (uint32_t)__cvta_generic_to_shared(sm);

    const int bp = blockIdx.y, m0 = blockIdx.x * 128;
    const int hh = bp >> 6, p = bp & 63;
    const int tid = threadIdx.x, lane = tid & 31, wid = tid >> 5;
    const int rbase = (wid & 3) * 32, cbase = (wid >> 2) * 32;
    const int lg = lane >> 2, lt = lane & 3;
    const int aRow = lane & 15, aCol = (lane >> 4) * 4;
    const int bRow = ((lane >> 4) & 1) * 8 + (lane & 7);
    const int bCol = ((lane >> 3) & 1) * 4;

    const uint32_t* A = g_attn + (size_t)bp * SS2 + (size_t)m0 * SEQ;
    const uint32_t* V = g_vT + (size_t)bp * HD * SEQ;

    float acc[2][4][4] = {};

    for (int ks = 0; ks < 6; ks++) {
        const int k0 = ks * 64;
        __syncthreads();
        #pragma unroll
        for (int i = 0; i < 16; i++) {
            int lin = i * 256 + tid;
            int row = lin >> 5, p2 = lin & 31;
            uint2 w = *(const uint2*)(A + (size_t)row * SEQ + k0 + p2 * 2);
            sm[row * 36 + p2]        = __byte_perm(w.x, w.y, 0x5410);
            sm[4608 + row * 36 + p2] = __byte_perm(w.x, w.y, 0x7632);
        }
        #pragma unroll
        for (int i = 0; i < 8; i++) {
            int lin = i * 256 + tid;
            int row = lin >> 5, p2 = lin & 31;
            uint2 w = *(const uint2*)(V + (size_t)row * SEQ + k0 + p2 * 2);
            sm[9216 + row * 36 + p2]  = __byte_perm(w.x, w.y, 0x5410);
            sm[11520 + row * 36 + p2] = __byte_perm(w.x, w.y, 0x7632);
        }
        __syncthreads();

        #pragma unroll
        for (int k16 = 0; k16 < 4; k16++) {
            const int ko = k16 * 8;
            uint32_t ah[2][4], al[2][4];
            #pragma unroll
            for (int mt = 0; mt < 2; mt++) {
                uint32_t aw = smb + ((rbase + mt * 16 + aRow) * 36 + aCol + ko) * 4;
                ldsm4(ah[mt][0], ah[mt][1], ah[mt][2], ah[mt][3], aw);
                ldsm4(al[mt][0], al[mt][1], al[mt][2], al[mt][3], aw + 18432);
            }
            #pragma unroll
            for (int pr = 0; pr < 2; pr++) {
                uint32_t bw = smb + 36864 + ((cbase + pr * 16 + bRow) * 36 + bCol + ko) * 4;
                uint32_t bh0, bh1, bh2, bh3, bl0, bl1, bl2, bl3;
                ldsm4(bh0, bh1, bh2, bh3, bw);
                ldsm4(bl0, bl1, bl2, bl3, bw + 9216);
                #pragma unroll
                for (int mt = 0; mt < 2; mt++) {
                    mma_f16(acc[mt][2 * pr],     ah[mt], bh0, bh1);
                    mma_f16(acc[mt][2 * pr],     ah[mt], bl0, bl1);
                    mma_f16(acc[mt][2 * pr],     al[mt], bh0, bh1);
                    mma_f16(acc[mt][2 * pr + 1], ah[mt], bh2, bh3);
                    mma_f16(acc[mt][2 * pr + 1], ah[mt], bl2, bl3);
                    mma_f16(acc[mt][2 * pr + 1], al[mt], bh2, bh3);
                }
            }
        }
    }

    #pragma unroll
    for (int mt = 0; mt < 2; mt++) {
        #pragma unroll
        for (int nt = 0; nt < 4; nt++) {
            #pragma unroll
            for (int cp = 0; cp < 4; cp++) {
                int q  = m0 + rbase + mt * 16 + lg + ((cp >= 2) ? 8 : 0);
                int dd = cbase + nt * 8 + lt * 2 + (cp & 1);
                g_c2_hl[((size_t)q * CIN + (dd * 8 + hh)) * 64 + p] =
                    split_h2(acc[mt][nt][cp]);
            }
        }
    }
}

// ---------------------------------------------------------------------------
extern "C" void kernel_launch(void* const* d_in, const int* in_sizes, int n_in,
                              void* d_out, int out_size)
{
    const float* inp       = (const float*)d_in[0];
    const float* attn_mask = (const float*)d_in[1];
    const int*   agent     = (const int*)  d_in[2];
    const float* w_in      = (const float*)d_in[3];
    const float* b_in      = (const float*)d_in[4];
    const float* w_out     = (const float*)d_in[5];
    const float* b_out     = (const float*)d_in[6];
    float*       out       = (float*)d_out;

    __half *wh_in, *wl_in, *wh_out, *wl_out;
    cudaGetSymbolAddress((void**)&wh_in,  g_wh_in);
    cudaGetSymbolAddress((void**)&wl_in,  g_wl_in);
    cudaGetSymbolAddress((void**)&wh_out, g_wh_out);
    cudaGetSymbolAddress((void**)&wl_out, g_wl_out);

    cudaFuncSetAttribute(conv_f16_kernel<2560, true>,
                         cudaFuncAttributeMaxDynamicSharedMemorySize, SMEM_BYTES);
    cudaFuncSetAttribute(conv_f16_kernel<512, false>,
                         cudaFuncAttributeMaxDynamicSharedMemorySize, SMEM_BYTES);
    cudaFuncSetAttribute(qk_mma_kernel,
                         cudaFuncAttributeMaxDynamicSharedMemorySize, QK_SMEM);
    cudaFuncSetAttribute(av_mma_kernel,
                         cudaFuncAttributeMaxDynamicSharedMemorySize, AV_SMEM);

    const int n_win  = 2560 * K9;
    const int n_wout = 512 * K9;
    split_w_kernel<<<(n_win + 255) / 256, 256>>>(w_in, wh_in, wl_in, n_win);
    split_w_kernel<<<(n_wout + 255) / 256, 256>>>(w_out, wh_out, wl_out, n_wout);

    // im2col expansion of raw input
    im2col_kernel<false><<<dim3(SEQ, 8), 256>>>(inp);

    // conv_in GEMM: emits packed Q/K planes + transposed V
    conv_f16_kernel<2560, true><<<dim3(20, 192), 256, SMEM_BYTES>>>(wh_in, wl_in, b_in, nullptr);

    // Scores on tensor cores: 1024 (bp,v) x 3x3 tiles of 128
    qk_mma_kernel<<<dim3(3, 3, 1024), 256, QK_SMEM>>>(attn_mask);

    // Dual softmax + agent blend -> packed attn
    softmax_kernel<<<dim3(SEQ, BP), 128>>>(agent);

    // attn @ V on tensor cores -> packed conv2 input
    av_mma_kernel<<<dim3(3, BP), 256, AV_SMEM>>>();

    // im2col expansion of attention output (packed source)
    im2col_kernel<true><<<dim3(SEQ, 8), 256>>>(nullptr);

    // conv_out GEMM
    conv_f16_kernel<512, false><<<dim3(4, 192), 256, SMEM_BYTES>>>(wh_out, wl_out, b_out, out);
}

// round 9
// speedup vs baseline: 1.0444x; 1.0444x over previous
#include <cuda_runtime.h>
#include <cuda_fp16.h>
#include <cstdint>

#define SEQ 384
#define CIN 512
#define HW  64
#define NH  8
#define HD  64
#define K9  (CIN * 9)        // 4608
#define BP  512              // NH * HW batch-pairs
#define NROWS (SEQ * HW)     // 24576 GEMM rows
#define SS2 (SEQ * SEQ)      // 147456

// Scratch (device globals; no runtime allocation)
__device__ uint32_t g_feats_hl[(size_t)4 * BP * SEQ * HD];  // [e][bp][n][dd] packed(hi,lo)
__device__ uint32_t g_vT[(size_t)BP * HD * SEQ];            // [bp][dd][n]   packed(hi,lo)
__device__ uint32_t g_attn[(size_t)BP * SS2];               // blended attn, packed(hi,lo)
__device__ uint32_t g_c2_hl[(size_t)SEQ * CIN * HW];        // conv2 input, packed(hi,lo)
__device__ __half   g_Ah[(size_t)NROWS * K9];               // im2col hi plane (k' = r*512+ci)
__device__ __half   g_Al[(size_t)NROWS * K9];               // im2col lo plane
__device__ __half   g_wh_in[(size_t)2560 * K9];             // weights hi, k'-order
__device__ __half   g_wl_in[(size_t)2560 * K9];
__device__ __half   g_wh_out[(size_t)512 * K9];
__device__ __half   g_wl_out[(size_t)512 * K9];

// ---------------------------------------------------------------------------
// helpers
// ---------------------------------------------------------------------------
__device__ __forceinline__ uint32_t split_h2(float x)
{
    __half hi = __float2half_rn(x);
    __half lo = __float2half_rn(x - __half2float(hi));
    return (uint32_t)__half_as_ushort(hi) | ((uint32_t)__half_as_ushort(lo) << 16);
}
__device__ __forceinline__ float unsplit_h2(uint32_t p)
{
    return __half2float(__ushort_as_half((unsigned short)(p & 0xFFFF)))
         + __half2float(__ushort_as_half((unsigned short)(p >> 16)));
}

__device__ __forceinline__ void mma_f16(float c[4], const uint32_t a[4],
                                        uint32_t b0, uint32_t b1)
{
    asm volatile(
        "mma.sync.aligned.m16n8k16.row.col.f32.f16.f16.f32 "
        "{%0,%1,%2,%3}, {%4,%5,%6,%7}, {%8,%9}, {%0,%1,%2,%3};"
        : "+f"(c[0]), "+f"(c[1]), "+f"(c[2]), "+f"(c[3])
        : "r"(a[0]), "r"(a[1]), "r"(a[2]), "r"(a[3]), "r"(b0), "r"(b1));
}
__device__ __forceinline__ void ldsm4(uint32_t& r0, uint32_t& r1, uint32_t& r2,
                                      uint32_t& r3, uint32_t addr)
{
    asm volatile("ldmatrix.sync.aligned.m8n8.x4.shared.b16 {%0,%1,%2,%3}, [%4];"
                 : "=r"(r0), "=r"(r1), "=r"(r2), "=r"(r3) : "r"(addr));
}
__device__ __forceinline__ void cpa16(uint32_t dst, const void* src)
{
    asm volatile("cp.async.cg.shared.global [%0], [%1], 16;" :: "r"(dst), "l"(src));
}

// ---------------------------------------------------------------------------
// Weight split + permute to k' = r*512 + ci order
// ---------------------------------------------------------------------------
__global__ void split_w_kernel(const float* __restrict__ w,
                               __half* __restrict__ wh, __half* __restrict__ wl, int n)
{
    int i = blockIdx.x * 256 + threadIdx.x;
    if (i >= n) return;
    int co = i / K9;
    int kn = i - co * K9;
    int r = kn >> 9, ci = kn & 511;
    float x = w[(size_t)co * K9 + ci * 9 + r];
    __half hi = __float2half_rn(x);
    wh[i] = hi;
    wl[i] = __float2half_rn(x - __half2float(hi));
}

// ---------------------------------------------------------------------------
// im2col expansion into hi/lo fp16 planes, k' = r*512 + ci.
// ---------------------------------------------------------------------------
template <bool PACKED>
__global__ __launch_bounds__(256) void im2col_kernel(const float* __restrict__ srcF)
{
    __shared__ ushort th[64][72];
    __shared__ ushort tl[64][72];
    const int n   = blockIdx.x;
    const int ci0 = blockIdx.y * 64;
    const int t   = threadIdx.x;

    {
        int sp4 = (t & 15) * 4;
        int ciL = t >> 4;
        #pragma unroll
        for (int pass = 0; pass < 4; pass++) {
            int ci = pass * 16 + ciL;
            if (PACKED) {
                uint4 w = *(const uint4*)(g_c2_hl + ((size_t)n * CIN + ci0 + ci) * 64 + sp4);
                uint32_t ws[4] = {w.x, w.y, w.z, w.w};
                #pragma unroll
                for (int j = 0; j < 4; j++) {
                    th[sp4 + j][ci] = (ushort)(ws[j] & 0xFFFF);
                    tl[sp4 + j][ci] = (ushort)(ws[j] >> 16);
                }
            } else {
                float4 v = *(const float4*)(srcF + ((size_t)n * CIN + ci0 + ci) * 64 + sp4);
                float vs[4] = {v.x, v.y, v.z, v.w};
                #pragma unroll
                for (int j = 0; j < 4; j++) {
                    __half hi = __float2half_rn(vs[j]);
                    __half lo = __float2half_rn(vs[j] - __half2float(hi));
                    th[sp4 + j][ci] = __half_as_ushort(hi);
                    tl[sp4 + j][ci] = __half_as_ushort(lo);
                }
            }
        }
    }
    __syncthreads();

    const int ciQ = t & 15;
    const int rg  = t >> 4;
    #pragma unroll
    for (int si = 0; si < 4; si++) {
        int sp = si * 16 + rg;
        int yy = sp >> 3, xx = sp & 7;
        size_t obase = (size_t)(n * 64 + sp) * K9 + ci0 + ciQ * 4;
        #pragma unroll
        for (int r = 0; r < 9; r++) {
            int y = yy + r / 3 - 1, x = xx + r % 3 - 1;
            uint2 vh = make_uint2(0, 0), vl = make_uint2(0, 0);
            if ((unsigned)y < 8u && (unsigned)x < 8u) {
                int spp = y * 8 + x;
                vh = *(const uint2*)&th[spp][ciQ * 4];
                vl = *(const uint2*)&tl[spp][ciQ * 4];
            }
            *(uint2*)&g_Ah[obase + (size_t)r * 512] = vh;
            *(uint2*)&g_Al[obase + (size_t)r * 512] = vl;
        }
    }
}

// ---------------------------------------------------------------------------
// fp16x3 GEMM conv (R7 form: double-buffered cp.async, two barriers/stage).
// ---------------------------------------------------------------------------
#define LDK2 20
#define STG_BYTES (4 * 128 * LDK2 * 4)
#define SMEM_BYTES (2 * STG_BYTES)

__device__ __forceinline__ void conv_fill(uint32_t base, int row0, int co0, int k0,
                                          int tid, const __half* gwh, const __half* gwl)
{
    #pragma unroll
    for (int h = 0; h < 2; h++) {
        int c = h * 256 + tid;
        int row = c >> 2, q = c & 3;
        uint32_t doff = (uint32_t)((row * LDK2 + q * 4) * 4);
        size_t aoff = (size_t)(row0 + row) * K9 + k0 + q * 8;
        size_t boff = (size_t)(co0 + row) * K9 + k0 + q * 8;
        cpa16(base + doff,         g_Ah + aoff);
        cpa16(base + 10240 + doff, g_Al + aoff);
        cpa16(base + 20480 + doff, gwh + boff);
        cpa16(base + 30720 + doff, gwl + boff);
    }
    asm volatile("cp.async.commit_group;" ::: "memory");
}

template <int CO, bool FIRST>
__global__ void __launch_bounds__(256, 2)
conv_f16_kernel(const __half* __restrict__ gwh,
                const __half* __restrict__ gwl,
                const float* __restrict__ bias,
                float* __restrict__ out)
{
    extern __shared__ uint32_t sm[];
    const uint32_t smb = (uint32_t)__cvta_generic_to_shared(sm);

    const int row0 = blockIdx.y * 128;
    const int co0  = blockIdx.x * 128;
    const int tid  = threadIdx.x;
    const int lane = tid & 31, wid = tid >> 5;
    const int rbase = (wid >> 1) * 32;
    const int cbase = (wid & 1) * 64;
    const int lg = lane >> 2, lt = lane & 3;

    const int aRow = lane & 15, aCol = (lane >> 4) * 4;
    const int bRow = ((lane >> 4) & 1) * 8 + (lane & 7);
    const int bCol = ((lane >> 3) & 1) * 4;

    float acc[2][8][4] = {};

    conv_fill(smb, row0, co0, 0, tid, gwh, gwl);

    const int NITER = K9 / 32;
    for (int it = 0; it < NITER; it++) {
        const int s = it & 1;
        asm volatile("cp.async.wait_group 0;" ::: "memory");
        __syncthreads();
        if (it + 1 < NITER)
            conv_fill(smb + (1 - s) * STG_BYTES, row0, co0, (it + 1) * 32, tid, gwh, gwl);

        const uint32_t base = smb + s * STG_BYTES;
        #pragma unroll
        for (int k16 = 0; k16 < 2; k16++) {
            const uint32_t ko = k16 * 8;
            uint32_t ah[2][4], al[2][4];
            #pragma unroll
            for (int mt = 0; mt < 2; mt++) {
                uint32_t aw = base + ((rbase + mt * 16 + aRow) * LDK2 + aCol + ko) * 4;
                ldsm4(ah[mt][0], ah[mt][1], ah[mt][2], ah[mt][3], aw);
                ldsm4(al[mt][0], al[mt][1], al[mt][2], al[mt][3], aw + 10240);
            }
            #pragma unroll
            for (int pr = 0; pr < 4; pr++) {
                uint32_t bw = base + 20480 +
                              ((cbase + pr * 16 + bRow) * LDK2 + bCol + ko) * 4;
                uint32_t bh0, bh1, bh2, bh3, bl0, bl1, bl2, bl3;
                ldsm4(bh0, bh1, bh2, bh3, bw);
                ldsm4(bl0, bl1, bl2, bl3, bw + 10240);
                #pragma unroll
                for (int mt = 0; mt < 2; mt++) {
                    mma_f16(acc[mt][2 * pr],     ah[mt], bh0, bh1);
                    mma_f16(acc[mt][2 * pr],     ah[mt], bl0, bl1);
                    mma_f16(acc[mt][2 * pr],     al[mt], bh0, bh1);
                    mma_f16(acc[mt][2 * pr + 1], ah[mt], bh2, bh3);
                    mma_f16(acc[mt][2 * pr + 1], ah[mt], bl2, bl3);
                    mma_f16(acc[mt][2 * pr + 1], al[mt], bh2, bh3);
                }
            }
        }
        __syncthreads();
    }

    // ---- epilogue ----
    #pragma unroll
    for (int mt = 0; mt < 2; mt++) {
        #pragma unroll
        for (int nt = 0; nt < 8; nt++) {
            #pragma unroll
            for (int cp = 0; cp < 4; cp++) {
                int row = row0 + rbase + mt * 16 + lg + ((cp >= 2) ? 8 : 0);
                int col = cbase + nt * 8 + lt * 2 + (cp & 1);
                int co  = co0 + col;
                float v = acc[mt][nt][cp] + bias[co];
                int n = row >> 6, sp = row & 63;
                if (FIRST) {
                    int e  = co >> 9;
                    int dd = (co >> 3) & 63;
                    int hh = co & 7;
                    int bpi = hh * 64 + sp;
                    uint32_t pv = split_h2(v);
                    if (e < 4)
                        g_feats_hl[(((size_t)e * BP + bpi) * SEQ + n) * HD + dd] = pv;
                    else
                        g_vT[((size_t)bpi * HD + dd) * SEQ + n] = pv;
                } else {
                    out[((size_t)n * CO + co) * 64 + sp] = v;
                }
            }
        }
    }
}

// ---------------------------------------------------------------------------
// Fused QK + dual softmax + agent blend.
// Grid (qtile=6, bp=512), 256 threads. Per variant v: stage Q (64 rows) once,
// loop 6 chunks of 64 K-rows: fp16x3 MMA -> raw scores into smem S[64][388];
// then warp-per-row softmax (scale+mask applied on read). v=0 writes packed
// a_same to g_attn; v=1 blends with agent mask and overwrites g_attn.
// smem words: S 0..24831 (64x388 f32), Qh 24832, Ql 27136, Kh 29440, Kl 31744
// (each plane 64 rows x 36 words). Total 136192 bytes.
// ---------------------------------------------------------------------------
#define FA_SMEM 136192
#define SST 388
#define QH_OFF 24832
#define QL_OFF 27136
#define KH_OFF 29440
#define KL_OFF 31744

__global__ void __launch_bounds__(256, 1)
fused_qk_softmax_kernel(const float* __restrict__ am, const int* __restrict__ agent)
{
    extern __shared__ uint32_t sm[];
    float* Sf = (float*)sm;
    const uint32_t smb = (uint32_t)__cvta_generic_to_shared(sm);

    const int m0 = blockIdx.x * 64;
    const int bp = blockIdx.y;
    const int head = bp >> 6;
    const int tid = threadIdx.x, lane = tid & 31, wid = tid >> 5;
    const int wq = (wid & 3) * 16;   // warp q-subtile (16 rows)
    const int wc = (wid >> 2) * 32;  // warp col-half within 64-col chunk
    const int lg = lane >> 2, lt = lane & 3;
    const int aRow = lane & 15, aCol = (lane >> 4) * 4;
    const int bRow = ((lane >> 4) & 1) * 8 + (lane & 7);
    const int bCol = ((lane >> 3) & 1) * 4;

    for (int v = 0; v < 2; v++) {
        // ---- stage Q (variant 2+v), rows m0..m0+63, split into hi/lo planes
        const uint32_t* Q = g_feats_hl + (((size_t)(2 + v) * BP + bp) * SEQ + m0) * HD;
        #pragma unroll
        for (int i = 0; i < 4; i++) {
            int lin = i * 256 + tid;              // 1024 uint4 slots
            int row = lin >> 4, q4 = lin & 15;
            uint4 w = *(const uint4*)(Q + (size_t)row * HD + q4 * 4);
            int o = row * 36 + q4 * 2;
            *(uint2*)&sm[QH_OFF + o] = make_uint2(__byte_perm(w.x, w.y, 0x5410),
                                                  __byte_perm(w.z, w.w, 0x5410));
            *(uint2*)&sm[QL_OFF + o] = make_uint2(__byte_perm(w.x, w.y, 0x7632),
                                                  __byte_perm(w.z, w.w, 0x7632));
        }

        const uint32_t* Kv = g_feats_hl + ((size_t)v * BP + bp) * SEQ * HD;
        for (int kc = 0; kc < 6; kc++) {
            __syncthreads();   // K/S buffers free (prev chunk MMA + prev softmax done)
            #pragma unroll
            for (int i = 0; i < 4; i++) {
                int lin = i * 256 + tid;
                int row = lin >> 4, q4 = lin & 15;
                uint4 w = *(const uint4*)(Kv + (size_t)(kc * 64 + row) * HD + q4 * 4);
                int o = row * 36 + q4 * 2;
                *(uint2*)&sm[KH_OFF + o] = make_uint2(__byte_perm(w.x, w.y, 0x5410),
                                                      __byte_perm(w.z, w.w, 0x5410));
                *(uint2*)&sm[KL_OFF + o] = make_uint2(__byte_perm(w.x, w.y, 0x7632),
                                                      __byte_perm(w.z, w.w, 0x7632));
            }
            __syncthreads();

            float acc[4][4] = {};
            #pragma unroll
            for (int k16 = 0; k16 < 4; k16++) {
                const int ko = k16 * 8;
                uint32_t ah[4], al[4];
                uint32_t aw = smb + (QH_OFF + (wq + aRow) * 36 + aCol + ko) * 4;
                ldsm4(ah[0], ah[1], ah[2], ah[3], aw);
                ldsm4(al[0], al[1], al[2], al[3], aw + (QL_OFF - QH_OFF) * 4);
                #pragma unroll
                for (int pr = 0; pr < 2; pr++) {
                    uint32_t bw = smb + (KH_OFF + (wc + pr * 16 + bRow) * 36 + bCol + ko) * 4;
                    uint32_t bh0, bh1, bh2, bh3, bl0, bl1, bl2, bl3;
                    ldsm4(bh0, bh1, bh2, bh3, bw);
                    ldsm4(bl0, bl1, bl2, bl3, bw + (KL_OFF - KH_OFF) * 4);
                    mma_f16(acc[pr * 2],     ah, bh0, bh1);
                    mma_f16(acc[pr * 2],     ah, bl0, bl1);
                    mma_f16(acc[pr * 2],     al, bh0, bh1);
                    mma_f16(acc[pr * 2 + 1], ah, bh2, bh3);
                    mma_f16(acc[pr * 2 + 1], ah, bl2, bl3);
                    mma_f16(acc[pr * 2 + 1], al, bh2, bh3);
                }
            }
            // raw scores -> smem
            #pragma unroll
            for (int nt = 0; nt < 4; nt++) {
                #pragma unroll
                for (int cp = 0; cp < 4; cp++) {
                    int q   = wq + lg + ((cp >= 2) ? 8 : 0);
                    int col = kc * 64 + wc + nt * 8 + lt * 2 + (cp & 1);
                    Sf[q * SST + col] = acc[nt][cp];
                }
            }
        }
        __syncthreads();

        // ---- softmax: warp-per-row (8 rows per warp), scale+mask on read
        #pragma unroll
        for (int r8 = 0; r8 < 8; r8++) {
            int row = wid * 8 + r8;
            int gq  = m0 + row;
            const float* amr = am + ((size_t)head * SEQ + gq) * SEQ;
            float e[12];
            float M = -1e30f;
            #pragma unroll
            for (int j = 0; j < 12; j++) {
                float s = Sf[row * SST + lane + 32 * j] * 0.125f + amr[lane + 32 * j];
                e[j] = s;
                M = fmaxf(M, s);
            }
            #pragma unroll
            for (int o = 16; o; o >>= 1) M = fmaxf(M, __shfl_xor_sync(~0u, M, o));
            float Z = 0.f;
            #pragma unroll
            for (int j = 0; j < 12; j++) { e[j] = __expf(e[j] - M); Z += e[j]; }
            #pragma unroll
            for (int o = 16; o; o >>= 1) Z += __shfl_xor_sync(~0u, Z, o);
            float rz = 1.f / Z;

            uint32_t* arow = g_attn + ((size_t)bp * SEQ + gq) * SEQ;
            if (v == 0) {
                #pragma unroll
                for (int j = 0; j < 12; j++)
                    arow[lane + 32 * j] = split_h2(e[j] * rz);
            } else {
                const int* mr = agent + ((size_t)head * SEQ + gq) * SEQ;
                #pragma unroll
                for (int j = 0; j < 12; j++) {
                    float a_same = unsplit_h2(arow[lane + 32 * j]);
                    float m = (float)mr[lane + 32 * j];
                    arow[lane + 32 * j] =
                        split_h2(m * a_same + (1.f - m) * e[j] * rz);
                }
            }
        }
        // next v: Q refill is safe (all MMA reads of Q ended before pre-softmax
        // barrier); S/K reuse protected by the kc-loop top barrier.
    }
}

// ---------------------------------------------------------------------------
// AV on fp16x3 MMA: O[bp][q][dd] = sum_k attn[q][k] * V[k][dd].
// ---------------------------------------------------------------------------
#define AV_SMEM (13824 * 4)   // 55296 bytes

__global__ void __launch_bounds__(256, 2)
av_mma_kernel()
{
    extern __shared__ uint32_t sm[];
    const uint32_t smb = (uint32_t)__cvta_generic_to_shared(sm);

    const int bp = blockIdx.y, m0 = blockIdx.x * 128;
    const int hh = bp >> 6, p = bp & 63;
    const int tid = threadIdx.x, lane = tid & 31, wid = tid >> 5;
    const int rbase = (wid & 3) * 32, cbase = (wid >> 2) * 32;
    const int lg = lane >> 2, lt = lane & 3;
    const int aRow = lane & 15, aCol = (lane >> 4) * 4;
    const int bRow = ((lane >> 4) & 1) * 8 + (lane & 7);
    const int bCol = ((lane >> 3) & 1) * 4;

    const uint32_t* A = g_attn + (size_t)bp * SS2 + (size_t)m0 * SEQ;
    const uint32_t* V = g_vT + (size_t)bp * HD * SEQ;

    float acc[2][4][4] = {};

    for (int ks = 0; ks < 6; ks++) {
        const int k0 = ks * 64;
        __syncthreads();
        #pragma unroll
        for (int i = 0; i < 16; i++) {
            int lin = i * 256 + tid;
            int row = lin >> 5, p2 = lin & 31;
            uint2 w = *(const uint2*)(A + (size_t)row * SEQ + k0 + p2 * 2);
            sm[row * 36 + p2]        = __byte_perm(w.x, w.y, 0x5410);
            sm[4608 + row * 36 + p2] = __byte_perm(w.x, w.y, 0x7632);
        }
        #pragma unroll
        for (int i = 0; i < 8; i++) {
            int lin = i * 256 + tid;
            int row = lin >> 5, p2 = lin & 31;
            uint2 w = *(const uint2*)(V + (size_t)row * SEQ + k0 + p2 * 2);
            sm[9216 + row * 36 + p2]  = __byte_perm(w.x, w.y, 0x5410);
            sm[11520 + row * 36 + p2] = __byte_perm(w.x, w.y, 0x7632);
        }
        __syncthreads();

        #pragma unroll
        for (int k16 = 0; k16 < 4; k16++) {
            const int ko = k16 * 8;
            uint32_t ah[2][4], al[2][4];
            #pragma unroll
            for (int mt = 0; mt < 2; mt++) {
                uint32_t aw = smb + ((rbase + mt * 16 + aRow) * 36 + aCol + ko) * 4;
                ldsm4(ah[mt][0], ah[mt][1], ah[mt][2], ah[mt][3], aw);
                ldsm4(al[mt][0], al[mt][1], al[mt][2], al[mt][3], aw + 18432);
            }
            #pragma unroll
            for (int pr = 0; pr < 2; pr++) {
                uint32_t bw = smb + 36864 + ((cbase + pr * 16 + bRow) * 36 + bCol + ko) * 4;
                uint32_t bh0, bh1, bh2, bh3, bl0, bl1, bl2, bl3;
                ldsm4(bh0, bh1, bh2, bh3, bw);
                ldsm4(bl0, bl1, bl2, bl3, bw + 9216);
                #pragma unroll
                for (int mt = 0; mt < 2; mt++) {
                    mma_f16(acc[mt][2 * pr],     ah[mt], bh0, bh1);
                    mma_f16(acc[mt][2 * pr],     ah[mt], bl0, bl1);
                    mma_f16(acc[mt][2 * pr],     al[mt], bh0, bh1);
                    mma_f16(acc[mt][2 * pr + 1], ah[mt], bh2, bh3);
                    mma_f16(acc[mt][2 * pr + 1], ah[mt], bl2, bl3);
                    mma_f16(acc[mt][2 * pr + 1], al[mt], bh2, bh3);
                }
            }
        }
    }

    #pragma unroll
    for (int mt = 0; mt < 2; mt++) {
        #pragma unroll
        for (int nt = 0; nt < 4; nt++) {
            #pragma unroll
            for (int cp = 0; cp < 4; cp++) {
                int q  = m0 + rbase + mt * 16 + lg + ((cp >= 2) ? 8 : 0);
                int dd = cbase + nt * 8 + lt * 2 + (cp & 1);
                g_c2_hl[((size_t)q * CIN + (dd * 8 + hh)) * 64 + p] =
                    split_h2(acc[mt][nt][cp]);
            }
        }
    }
}

// ---------------------------------------------------------------------------
extern "C" void kernel_launch(void* const* d_in, const int* in_sizes, int n_in,
                              void* d_out, int out_size)
{
    const float* inp       = (const float*)d_in[0];
    const float* attn_mask = (const float*)d_in[1];
    const int*   agent     = (const int*)  d_in[2];
    const float* w_in      = (const float*)d_in[3];
    const float* b_in      = (const float*)d_in[4];
    const float* w_out     = (const float*)d_in[5];
    const float* b_out     = (const float*)d_in[6];
    float*       out       = (float*)d_out;

    __half *wh_in, *wl_in, *wh_out, *wl_out;
    cudaGetSymbolAddress((void**)&wh_in,  g_wh_in);
    cudaGetSymbolAddress((void**)&wl_in,  g_wl_in);
    cudaGetSymbolAddress((void**)&wh_out, g_wh_out);
    cudaGetSymbolAddress((void**)&wl_out, g_wl_out);

    cudaFuncSetAttribute(conv_f16_kernel<2560, true>,
                         cudaFuncAttributeMaxDynamicSharedMemorySize, SMEM_BYTES);
    cudaFuncSetAttribute(conv_f16_kernel<512, false>,
                         cudaFuncAttributeMaxDynamicSharedMemorySize, SMEM_BYTES);
    cudaFuncSetAttribute(fused_qk_softmax_kernel,
                         cudaFuncAttributeMaxDynamicSharedMemorySize, FA_SMEM);
    cudaFuncSetAttribute(av_mma_kernel,
                         cudaFuncAttributeMaxDynamicSharedMemorySize, AV_SMEM);

    const int n_win  = 2560 * K9;
    const int n_wout = 512 * K9;
    split_w_kernel<<<(n_win + 255) / 256, 256>>>(w_in, wh_in, wl_in, n_win);
    split_w_kernel<<<(n_wout + 255) / 256, 256>>>(w_out, wh_out, wl_out, n_wout);

    // im2col expansion of raw input
    im2col_kernel<false><<<dim3(SEQ, 8), 256>>>(inp);

    // conv_in GEMM: emits packed Q/K planes + transposed V
    conv_f16_kernel<2560, true><<<dim3(20, 192), 256, SMEM_BYTES>>>(wh_in, wl_in, b_in, nullptr);

    // fused scores + dual softmax + agent blend -> packed attn
    fused_qk_softmax_kernel<<<dim3(6, BP), 256, FA_SMEM>>>(attn_mask, agent);

    // attn @ V on tensor cores -> packed conv2 input
    av_mma_kernel<<<dim3(3, BP), 256, AV_SMEM>>>();

    // im2col expansion of attention output (packed source)
    im2col_kernel<true><<<dim3(SEQ, 8), 256>>>(nullptr);

    // conv_out GEMM
    conv_f16_kernel<512, false><<<dim3(4, 192), 256, SMEM_BYTES>>>(wh_out, wl_out, b_out, out);
}